// round 3
// baseline (speedup 1.0000x reference)
#include <cuda_runtime.h>
#include <cstdint>

// Problem constants
#define T_STEPS 512
#define B_TOT   1024
#define IN_DIM  128
#define H_DIM   256
#define OUT_DIM 4
#define BB      8            // batch rows per block (sequential kernel)
#define NBLK_C  (B_TOT / BB) // 128
#define NTHR_C  288          // 8 GEMM warps + 1 logits warp

#define HS0_OFF ((size_t)T_STEPS * B_TOT * OUT_DIM)  // 2,097,152

typedef unsigned long long u64;

// ---------------- scratch (no cudaMalloc allowed) -------------------------
__device__ float g_xproj[(size_t)T_STEPS * B_TOT * H_DIM];   // x@Wx^T + b_i2h
__device__ float g_outx [(size_t)T_STEPS * B_TOT * OUT_DIM]; // x@Wox^T + b_i2o

// ---------------- helpers --------------------------------------------------
__device__ __forceinline__ void ffma2(u64& d, u64 a, u64 b) {
    asm("fma.rn.f32x2 %0, %1, %2, %0;" : "+l"(d) : "l"(a), "l"(b));
}
__device__ __forceinline__ u64 pack2(float a, float b) {
    u64 r; asm("mov.b64 %0, {%1, %2};" : "=l"(r) : "f"(a), "f"(b)); return r;
}
__device__ __forceinline__ float hsum2(u64 a) {
    float x, y; asm("mov.b64 {%0,%1}, %2;" : "=f"(x), "=f"(y) : "l"(a));
    return x + y;
}

// ===========================================================================
// Kernel A: X_proj = inp @ Wx^T + b_i2h    (M=524288, N=256, K=128)
// CTA tile 128x256, 512 threads, thread tile 8 rows x 8 cols.
// X transposed in smem -> a-operand is 2 broadcast LDS.128 per k.
// W cols split {4*lane, 128+4*lane} -> conflict-free LDS.128.
// ===========================================================================
#define XT_PAD 132
#define WT_PAD 260
#define A_SMEM_BYTES ((128 * XT_PAD + 128 * WT_PAD) * 4)   // 200,704 B

extern __shared__ float smemA[];

__global__ void __launch_bounds__(512, 1)
xproj_kernel(const float* __restrict__ inp,
             const float* __restrict__ W_i2h,
             const float* __restrict__ b_i2h)
{
    float* sXt = smemA;                   // [k][row]  128 x 132
    float* sWt = smemA + 128 * XT_PAD;    // [k][col]  128 x 260

    const int tid = threadIdx.x;
    const int m0  = blockIdx.x * 128;

    // ---- fill transposed X tile ----
    const float4* in4 = (const float4*)inp;
    #pragma unroll
    for (int i = 0; i < 8; ++i) {
        int idx = tid + i * 512;
        int row = idx >> 5, k4 = idx & 31;
        float4 v = in4[(size_t)(m0 + row) * 32 + k4];
        sXt[(k4 * 4 + 0) * XT_PAD + row] = v.x;
        sXt[(k4 * 4 + 1) * XT_PAD + row] = v.y;
        sXt[(k4 * 4 + 2) * XT_PAD + row] = v.z;
        sXt[(k4 * 4 + 3) * XT_PAD + row] = v.w;
    }
    // ---- fill transposed W (x-part: first 32 f4 of each 96-f4 row) ----
    const float4* w4 = (const float4*)W_i2h;
    #pragma unroll
    for (int i = 0; i < 16; ++i) {
        int idx = tid + i * 512;
        int col = idx >> 5, k4 = idx & 31;
        float4 v = w4[(size_t)col * 96 + k4];
        sWt[(k4 * 4 + 0) * WT_PAD + col] = v.x;
        sWt[(k4 * 4 + 1) * WT_PAD + col] = v.y;
        sWt[(k4 * 4 + 2) * WT_PAD + col] = v.z;
        sWt[(k4 * 4 + 3) * WT_PAD + col] = v.w;
    }
    __syncthreads();

    const int warp = tid >> 5;            // 0..15 -> rows 8*warp..8*warp+7
    const int lane = tid & 31;            // cols {4*lane..+3, 128+4*lane..+3}
    const float* xr = sXt + 8 * warp;
    const float* wc = sWt + 4 * lane;

    u64 acc[8][4];
    {
        float4 b0 = *(const float4*)(b_i2h + 4 * lane);
        float4 b1 = *(const float4*)(b_i2h + 128 + 4 * lane);
        u64 p0 = pack2(b0.x, b0.y), p1 = pack2(b0.z, b0.w);
        u64 p2 = pack2(b1.x, b1.y), p3 = pack2(b1.z, b1.w);
        #pragma unroll
        for (int r = 0; r < 8; ++r) {
            acc[r][0] = p0; acc[r][1] = p1; acc[r][2] = p2; acc[r][3] = p3;
        }
    }

    #pragma unroll 4
    for (int k = 0; k < 128; ++k) {
        float4 a0 = *(const float4*)(xr + (size_t)k * XT_PAD);       // rows 0-3 (bcast)
        float4 a1 = *(const float4*)(xr + (size_t)k * XT_PAD + 4);   // rows 4-7 (bcast)
        float4 w0 = *(const float4*)(wc + (size_t)k * WT_PAD);
        float4 w1 = *(const float4*)(wc + (size_t)k * WT_PAD + 128);
        u64 wp0 = pack2(w0.x, w0.y), wp1 = pack2(w0.z, w0.w);
        u64 wp2 = pack2(w1.x, w1.y), wp3 = pack2(w1.z, w1.w);
        float ar[8] = {a0.x, a0.y, a0.z, a0.w, a1.x, a1.y, a1.z, a1.w};
        #pragma unroll
        for (int r = 0; r < 8; ++r) {
            u64 aa = pack2(ar[r], ar[r]);
            ffma2(acc[r][0], wp0, aa);
            ffma2(acc[r][1], wp1, aa);
            ffma2(acc[r][2], wp2, aa);
            ffma2(acc[r][3], wp3, aa);
        }
    }

    float* xp = g_xproj + ((size_t)(m0 + 8 * warp)) * 256 + 4 * lane;
    #pragma unroll
    for (int r = 0; r < 8; ++r) {
        float l0, h0, l1, h1;
        asm("mov.b64 {%0,%1}, %2;" : "=f"(l0), "=f"(h0) : "l"(acc[r][0]));
        asm("mov.b64 {%0,%1}, %2;" : "=f"(l1), "=f"(h1) : "l"(acc[r][1]));
        *(float4*)(xp + (size_t)r * 256) = make_float4(l0, h0, l1, h1);
        asm("mov.b64 {%0,%1}, %2;" : "=f"(l0), "=f"(h0) : "l"(acc[r][2]));
        asm("mov.b64 {%0,%1}, %2;" : "=f"(l1), "=f"(h1) : "l"(acc[r][3]));
        *(float4*)(xp + (size_t)r * 256 + 128) = make_float4(l0, h0, l1, h1);
    }
}

// ===========================================================================
// Kernel B: OutX = inp @ Wo_x^T + b_i2o   (memory-bound)
// ===========================================================================
__global__ void __launch_bounds__(256, 4)
outx_kernel(const float* __restrict__ inp,
            const float* __restrict__ W_i2o,
            const float* __restrict__ b_i2o)
{
    __shared__ float sW[4 * 128];
    __shared__ float sB[4];
    const int tid = threadIdx.x;
    if (tid < 128) {
        #pragma unroll
        for (int o = 0; o < 4; ++o) sW[o * 128 + tid] = W_i2o[o * 384 + tid];
    }
    if (tid < 4) sB[tid] = b_i2o[tid];
    __syncthreads();

    size_t row = (size_t)blockIdx.x * 256 + tid;
    const float4* x4 = (const float4*)inp + row * 32;
    float a0 = sB[0], a1 = sB[1], a2 = sB[2], a3 = sB[3];
    const float4* w0 = (const float4*)sW;
    const float4* w1 = (const float4*)(sW + 128);
    const float4* w2 = (const float4*)(sW + 256);
    const float4* w3 = (const float4*)(sW + 384);
    #pragma unroll 8
    for (int k4 = 0; k4 < 32; ++k4) {
        float4 x = x4[k4];
        float4 v;
        v = w0[k4]; a0 += x.x * v.x + x.y * v.y + x.z * v.z + x.w * v.w;
        v = w1[k4]; a1 += x.x * v.x + x.y * v.y + x.z * v.z + x.w * v.w;
        v = w2[k4]; a2 += x.x * v.x + x.y * v.y + x.z * v.z + x.w * v.w;
        v = w3[k4]; a3 += x.x * v.x + x.y * v.y + x.z * v.z + x.w * v.w;
    }
    *(float4*)&g_outx[row * 4] = make_float4(a0, a1, a2, a3);
}

// ===========================================================================
// Kernel C: sequential recurrence. 128 CTAs x 8 batch rows, 512 steps.
// GEMM threads (256): thread = 2 cols x 4 rows. Warp spans 4 rows ->
// h-broadcast wf halved vs 1x8 layout. W k4 0..15 in regs, 16..63 in smem.
// Warp 8: logits + argmax with 4-way split accumulator.
// ===========================================================================
#define WPAD4 49
#define C_SW_F   (256 * WPAD4 * 4)            // 50176 floats
#define C_SH_F   (C_SW_F)
#define C_SWO_F  (C_SH_F + BB * 256)
#define C_SACT_F (C_SWO_F + 4 * 260)
#define C_SOUT_F (C_SACT_F + 4 * 256)
#define C_SQ_F   (C_SOUT_F + 32)
#define C_SMEM_BYTES ((C_SQ_F + 8) * 4)       // ~217.4 KB

extern __shared__ float smemC[];

__global__ void __launch_bounds__(NTHR_C, 1)
rnn_seq_kernel(const float* __restrict__ hidden,
               const float* __restrict__ W_i2h,
               const float* __restrict__ W_i2o,
               const float* __restrict__ actions,
               float* __restrict__ out)
{
    float* sW   = smemC;
    float* sH   = smemC + C_SH_F;
    float* sWo  = smemC + C_SWO_F;
    float* sAct = smemC + C_SACT_F;
    float* sOut = smemC + C_SOUT_F;
    int*   sQ   = (int*)(smemC + C_SQ_F);

    const int tid = threadIdx.x;
    const int bs  = blockIdx.x * BB;

    const float4* Wh4 = (const float4*)W_i2h;   // [256][96] f4 per row

    // ---- one-time fills ---------------------------------------------------
    if (tid < 256) {
        // smem W: k4 16..63 of column `tid`
        #pragma unroll 8
        for (int k4 = 16; k4 < 64; ++k4)
            ((float4*)sW)[tid * WPAD4 + (k4 - 16)] = Wh4[(size_t)tid * 96 + 32 + k4];
        #pragma unroll
        for (int r = 0; r < BB; ++r)
            sH[r * 256 + tid] = hidden[(size_t)(bs + r) * 256 + tid];
        #pragma unroll
        for (int i = tid; i < 4 * 256; i += 256)
            sWo[(i >> 8) * 260 + (i & 255)] = W_i2o[(i >> 8) * 384 + 128 + (i & 255)];
        #pragma unroll
        for (int i = tid; i < 4 * 256; i += 256) sAct[i] = actions[i];
    }

    // ---- thread mapping & register W ---------------------------------------
    const int c2    = tid & 127;          // col base: cols {c2, c2+128}
    const int rg    = (tid >> 7) & 1;     // row group
    const int rbase = rg * 4;
    const int j0 = c2, j1 = c2 + 128;

    u64 w0lo[16], w0hi[16], w1lo[16], w1hi[16];
    if (tid < 256) {
        #pragma unroll
        for (int k4 = 0; k4 < 16; ++k4) {
            float4 v0 = Wh4[(size_t)j0 * 96 + 32 + k4];
            float4 v1 = Wh4[(size_t)j1 * 96 + 32 + k4];
            w0lo[k4] = pack2(v0.x, v0.y); w0hi[k4] = pack2(v0.z, v0.w);
            w1lo[k4] = pack2(v1.x, v1.y); w1hi[k4] = pack2(v1.z, v1.w);
        }
    }
    __syncthreads();

    const ulonglong2* sW0 = (const ulonglong2*)sW + (size_t)j0 * WPAD4;
    const ulonglong2* sW1 = (const ulonglong2*)sW + (size_t)j1 * WPAD4;

    // X_proj prefetch for t=0
    float xp0[4], xp1[4];
    if (tid < 256) {
        #pragma unroll
        for (int r = 0; r < 4; ++r) {
            xp0[r] = g_xproj[((size_t)0 * B_TOT + bs + rbase + r) * 256 + j0];
            xp1[r] = g_xproj[((size_t)0 * B_TOT + bs + rbase + r) * 256 + j1];
        }
    }
    float oxCur = 0.f;
    const int lane = tid - 256;
    if (tid >= 256) oxCur = g_outx[((size_t)0 * B_TOT + bs) * 4 + lane];

    for (int t = 0; t < T_STEPS; ++t) {
        const int tn = (t + 1 < T_STEPS) ? (t + 1) : t;

        if (tid < 256) {
            u64 a0l[4], a0h[4], a1l[4], a1h[4];
            #pragma unroll
            for (int r = 0; r < 4; ++r) {
                a0l[r] = pack2(xp0[r], 0.f); a0h[r] = 0ull;
                a1l[r] = pack2(xp1[r], 0.f); a1h[r] = 0ull;
            }
            #pragma unroll
            for (int r = 0; r < 4; ++r) {
                xp0[r] = g_xproj[((size_t)tn * B_TOT + bs + rbase + r) * 256 + j0];
                xp1[r] = g_xproj[((size_t)tn * B_TOT + bs + rbase + r) * 256 + j1];
            }

            const float* hb = sH + rbase * 256;

            // ---- K part 1: register W ----
            #pragma unroll
            for (int k4 = 0; k4 < 16; ++k4) {
                #pragma unroll
                for (int r = 0; r < 4; ++r) {
                    ulonglong2 c = *(const ulonglong2*)(hb + r * 256 + k4 * 4);
                    ffma2(a0l[r], w0lo[k4], c.x); ffma2(a0h[r], w0hi[k4], c.y);
                    ffma2(a1l[r], w1lo[k4], c.x); ffma2(a1h[r], w1hi[k4], c.y);
                }
            }
            // ---- K part 2: smem W ----
            #pragma unroll 4
            for (int k4 = 16; k4 < 64; ++k4) {
                ulonglong2 w0 = sW0[k4 - 16];
                ulonglong2 w1 = sW1[k4 - 16];
                #pragma unroll
                for (int r = 0; r < 4; ++r) {
                    ulonglong2 c = *(const ulonglong2*)(hb + r * 256 + k4 * 4);
                    ffma2(a0l[r], w0.x, c.x); ffma2(a0h[r], w0.y, c.y);
                    ffma2(a1l[r], w1.x, c.x); ffma2(a1h[r], w1.y, c.y);
                }
            }

            __syncthreads();   // #2: sQ ready, all sH reads done

            #pragma unroll
            for (int r = 0; r < 4; ++r) {
                int rr = rbase + r;
                float z0 = hsum2(a0l[r]) + hsum2(a0h[r]);
                float z1 = hsum2(a1l[r]) + hsum2(a1h[r]);
                float h0 = tanhf(z0);
                float h1 = tanhf(z1);
                if (t == 0) {
                    out[HS0_OFF + (size_t)(bs + rr) * 256 + j0] = h0;
                    out[HS0_OFF + (size_t)(bs + rr) * 256 + j1] = h1;
                }
                int q = sQ[rr];
                sH[rr * 256 + j0] = h0 * (1.0f + sAct[q * 256 + j0]);
                sH[rr * 256 + j1] = h1 * (1.0f + sAct[q * 256 + j1]);
            }
        } else if (lane < 32) {
            // ---- logits warp: 4-way split accumulator ----
            const int r = lane >> 2, o = lane & 3;
            const float4* hp = (const float4*)(sH + r * 256);
            const float4* wp = (const float4*)(sWo + o * 260);
            float p0 = oxCur, p1 = 0.f, p2 = 0.f, p3 = 0.f;
            #pragma unroll 4
            for (int k4 = 0; k4 < 64; k4 += 4) {
                float4 h0 = hp[k4],     w0 = wp[k4];
                float4 h1 = hp[k4 + 1], w1 = wp[k4 + 1];
                float4 h2 = hp[k4 + 2], w2 = wp[k4 + 2];
                float4 h3 = hp[k4 + 3], w3 = wp[k4 + 3];
                p0 += h0.x * w0.x + h0.y * w0.y + h0.z * w0.z + h0.w * w0.w;
                p1 += h1.x * w1.x + h1.y * w1.y + h1.z * w1.z + h1.w * w1.w;
                p2 += h2.x * w2.x + h2.y * w2.y + h2.z * w2.z + h2.w * w2.w;
                p3 += h3.x * w3.x + h3.y * w3.y + h3.z * w3.z + h3.w * w3.w;
            }
            float acc = (p0 + p1) + (p2 + p3);
            sOut[lane] = acc;
            __syncwarp();
            if (o == 0) {
                float best = sOut[r * 4]; int q = 0;
                #pragma unroll
                for (int oo = 1; oo < 4; ++oo) {
                    float v = sOut[r * 4 + oo];
                    if (v > best) { best = v; q = oo; }
                }
                sQ[r] = q;
            }
            out[((size_t)t * B_TOT + bs) * 4 + lane] = acc;
            oxCur = g_outx[((size_t)tn * B_TOT + bs) * 4 + lane];

            __syncthreads();   // #2
        } else {
            __syncthreads();   // #2
        }

        __syncthreads();       // #1: new h visible to everyone
    }
}

// ===========================================================================
extern "C" void kernel_launch(void* const* d_in, const int* in_sizes, int n_in,
                              void* d_out, int out_size)
{
    const float* inp     = (const float*)d_in[0];
    const float* hidden  = (const float*)d_in[1];
    const float* W_i2h   = (const float*)d_in[2];
    const float* b_i2h   = (const float*)d_in[3];
    const float* W_i2o   = (const float*)d_in[4];
    const float* b_i2o   = (const float*)d_in[5];
    const float* actions = (const float*)d_in[6];
    float* out = (float*)d_out;

    cudaFuncSetAttribute(xproj_kernel,
                         cudaFuncAttributeMaxDynamicSharedMemorySize, A_SMEM_BYTES);
    cudaFuncSetAttribute(rnn_seq_kernel,
                         cudaFuncAttributeMaxDynamicSharedMemorySize, C_SMEM_BYTES);

    xproj_kernel<<<(T_STEPS * B_TOT) / 128, 512, A_SMEM_BYTES>>>(inp, W_i2h, b_i2h);
    outx_kernel<<<(T_STEPS * B_TOT) / 256, 256>>>(inp, W_i2o, b_i2o);
    rnn_seq_kernel<<<NBLK_C, NTHR_C, C_SMEM_BYTES>>>(hidden, W_i2h, W_i2o,
                                                     actions, out);
}

// round 4
// speedup vs baseline: 1.0807x; 1.0807x over previous
#include <cuda_runtime.h>
#include <cstdint>

// Problem constants
#define T_STEPS 512
#define B_TOT   1024
#define IN_DIM  128
#define H_DIM   256
#define OUT_DIM 4
#define BB      8            // batch rows per block (sequential kernel)
#define NBLK_C  (B_TOT / BB) // 128
#define NTHR_C  544          // 16 GEMM warps + 1 logits warp

#define HS0_OFF ((size_t)T_STEPS * B_TOT * OUT_DIM)  // 2,097,152

typedef unsigned long long u64;

// ---------------- scratch (no cudaMalloc allowed) -------------------------
__device__ float g_xproj[(size_t)T_STEPS * B_TOT * H_DIM];   // x@Wx^T + b_i2h
__device__ float g_outx [(size_t)T_STEPS * B_TOT * OUT_DIM]; // x@Wox^T + b_i2o

// ---------------- helpers --------------------------------------------------
__device__ __forceinline__ void ffma2(u64& d, u64 a, u64 b) {
    asm("fma.rn.f32x2 %0, %1, %2, %0;" : "+l"(d) : "l"(a), "l"(b));
}
__device__ __forceinline__ u64 pack2(float a, float b) {
    u64 r; asm("mov.b64 %0, {%1, %2};" : "=l"(r) : "f"(a), "f"(b)); return r;
}
__device__ __forceinline__ float hsum2(u64 a) {
    float x, y; asm("mov.b64 {%0,%1}, %2;" : "=f"(x), "=f"(y) : "l"(a));
    return x + y;
}

// ===========================================================================
// Kernel A: X_proj = inp @ Wx^T + b_i2h    (M=524288, N=256, K=128)
// (unchanged from R3: 980us, fma=44.8%)
// ===========================================================================
#define XT_PAD 132
#define WT_PAD 260
#define A_SMEM_BYTES ((128 * XT_PAD + 128 * WT_PAD) * 4)   // 200,704 B

extern __shared__ float smemA[];

__global__ void __launch_bounds__(512, 1)
xproj_kernel(const float* __restrict__ inp,
             const float* __restrict__ W_i2h,
             const float* __restrict__ b_i2h)
{
    float* sXt = smemA;                   // [k][row]  128 x 132
    float* sWt = smemA + 128 * XT_PAD;    // [k][col]  128 x 260

    const int tid = threadIdx.x;
    const int m0  = blockIdx.x * 128;

    const float4* in4 = (const float4*)inp;
    #pragma unroll
    for (int i = 0; i < 8; ++i) {
        int idx = tid + i * 512;
        int row = idx >> 5, k4 = idx & 31;
        float4 v = in4[(size_t)(m0 + row) * 32 + k4];
        sXt[(k4 * 4 + 0) * XT_PAD + row] = v.x;
        sXt[(k4 * 4 + 1) * XT_PAD + row] = v.y;
        sXt[(k4 * 4 + 2) * XT_PAD + row] = v.z;
        sXt[(k4 * 4 + 3) * XT_PAD + row] = v.w;
    }
    const float4* w4 = (const float4*)W_i2h;
    #pragma unroll
    for (int i = 0; i < 16; ++i) {
        int idx = tid + i * 512;
        int col = idx >> 5, k4 = idx & 31;
        float4 v = w4[(size_t)col * 96 + k4];
        sWt[(k4 * 4 + 0) * WT_PAD + col] = v.x;
        sWt[(k4 * 4 + 1) * WT_PAD + col] = v.y;
        sWt[(k4 * 4 + 2) * WT_PAD + col] = v.z;
        sWt[(k4 * 4 + 3) * WT_PAD + col] = v.w;
    }
    __syncthreads();

    const int warp = tid >> 5;
    const int lane = tid & 31;
    const float* xr = sXt + 8 * warp;
    const float* wc = sWt + 4 * lane;

    u64 acc[8][4];
    {
        float4 b0 = *(const float4*)(b_i2h + 4 * lane);
        float4 b1 = *(const float4*)(b_i2h + 128 + 4 * lane);
        u64 p0 = pack2(b0.x, b0.y), p1 = pack2(b0.z, b0.w);
        u64 p2 = pack2(b1.x, b1.y), p3 = pack2(b1.z, b1.w);
        #pragma unroll
        for (int r = 0; r < 8; ++r) {
            acc[r][0] = p0; acc[r][1] = p1; acc[r][2] = p2; acc[r][3] = p3;
        }
    }

    #pragma unroll 4
    for (int k = 0; k < 128; ++k) {
        float4 a0 = *(const float4*)(xr + (size_t)k * XT_PAD);
        float4 a1 = *(const float4*)(xr + (size_t)k * XT_PAD + 4);
        float4 w0 = *(const float4*)(wc + (size_t)k * WT_PAD);
        float4 w1 = *(const float4*)(wc + (size_t)k * WT_PAD + 128);
        u64 wp0 = pack2(w0.x, w0.y), wp1 = pack2(w0.z, w0.w);
        u64 wp2 = pack2(w1.x, w1.y), wp3 = pack2(w1.z, w1.w);
        float ar[8] = {a0.x, a0.y, a0.z, a0.w, a1.x, a1.y, a1.z, a1.w};
        #pragma unroll
        for (int r = 0; r < 8; ++r) {
            u64 aa = pack2(ar[r], ar[r]);
            ffma2(acc[r][0], wp0, aa);
            ffma2(acc[r][1], wp1, aa);
            ffma2(acc[r][2], wp2, aa);
            ffma2(acc[r][3], wp3, aa);
        }
    }

    float* xp = g_xproj + ((size_t)(m0 + 8 * warp)) * 256 + 4 * lane;
    #pragma unroll
    for (int r = 0; r < 8; ++r) {
        float l0, h0, l1, h1;
        asm("mov.b64 {%0,%1}, %2;" : "=f"(l0), "=f"(h0) : "l"(acc[r][0]));
        asm("mov.b64 {%0,%1}, %2;" : "=f"(l1), "=f"(h1) : "l"(acc[r][1]));
        *(float4*)(xp + (size_t)r * 256) = make_float4(l0, h0, l1, h1);
        asm("mov.b64 {%0,%1}, %2;" : "=f"(l0), "=f"(h0) : "l"(acc[r][2]));
        asm("mov.b64 {%0,%1}, %2;" : "=f"(l1), "=f"(h1) : "l"(acc[r][3]));
        *(float4*)(xp + (size_t)r * 256 + 128) = make_float4(l0, h0, l1, h1);
    }
}

// ===========================================================================
// Kernel B: OutX = inp @ Wo_x^T + b_i2o   (memory-bound)
// ===========================================================================
__global__ void __launch_bounds__(256, 4)
outx_kernel(const float* __restrict__ inp,
            const float* __restrict__ W_i2o,
            const float* __restrict__ b_i2o)
{
    __shared__ float sW[4 * 128];
    __shared__ float sB[4];
    const int tid = threadIdx.x;
    if (tid < 128) {
        #pragma unroll
        for (int o = 0; o < 4; ++o) sW[o * 128 + tid] = W_i2o[o * 384 + tid];
    }
    if (tid < 4) sB[tid] = b_i2o[tid];
    __syncthreads();

    size_t row = (size_t)blockIdx.x * 256 + tid;
    const float4* x4 = (const float4*)inp + row * 32;
    float a0 = sB[0], a1 = sB[1], a2 = sB[2], a3 = sB[3];
    const float4* w0 = (const float4*)sW;
    const float4* w1 = (const float4*)(sW + 128);
    const float4* w2 = (const float4*)(sW + 256);
    const float4* w3 = (const float4*)(sW + 384);
    #pragma unroll 8
    for (int k4 = 0; k4 < 32; ++k4) {
        float4 x = x4[k4];
        float4 v;
        v = w0[k4]; a0 += x.x * v.x + x.y * v.y + x.z * v.z + x.w * v.w;
        v = w1[k4]; a1 += x.x * v.x + x.y * v.y + x.z * v.z + x.w * v.w;
        v = w2[k4]; a2 += x.x * v.x + x.y * v.y + x.z * v.z + x.w * v.w;
        v = w3[k4]; a3 += x.x * v.x + x.y * v.y + x.z * v.z + x.w * v.w;
    }
    *(float4*)&g_outx[row * 4] = make_float4(a0, a1, a2, a3);
}

// ===========================================================================
// Kernel C: sequential recurrence, K-SPLIT version.
// 128 CTAs x 8 batch rows, 512 steps. 512 GEMM threads:
//   thread = (col = tid&255, khalf = tid>>8), 8 rows x 1 col x K/2.
//   khalf's k4 range = khalf*32 + [0..31]; first 8 k4 in regs, 24 in smem.
//   khalf1 adds X_proj and writes fp32 partials; khalf0 reduces + tanh + gate.
// Warp 16 (tid 512..543): logits + argmax.
// ===========================================================================
#define WPAD2 49   // ulonglong2 stride per column (784 B) -> conflict-free
// smem floats:
#define C_SW_F   (256 * WPAD2 * 4)            // 50176 floats (ull2 x 49 x 256)
#define C_SH_F   (C_SW_F)                      // sH  : 2048 f
#define C_SRED_F (C_SH_F + BB * 256)           // sRed: 2048 f
#define C_SWO_F  (C_SRED_F + BB * 256)         // sWo : 1040 f
#define C_SACT_F (C_SWO_F + 4 * 260)           // sAct: 1024 f
#define C_SOUT_F (C_SACT_F + 4 * 256)          // sOut: 32 f
#define C_SQ_F   (C_SOUT_F + 32)               // sQ  : 8 i
#define C_SMEM_BYTES ((C_SQ_F + 8) * 4)        // 225,536 B

extern __shared__ float smemC[];

__global__ void __launch_bounds__(NTHR_C, 1)
rnn_seq_kernel(const float* __restrict__ hidden,
               const float* __restrict__ W_i2h,
               const float* __restrict__ W_i2o,
               const float* __restrict__ actions,
               float* __restrict__ out)
{
    ulonglong2* sW2 = (ulonglong2*)smemC;       // [col][WPAD2], slots 0..47 used
    float* sH   = smemC + C_SH_F;
    float* sRed = smemC + C_SRED_F;
    float* sWo  = smemC + C_SWO_F;
    float* sAct = smemC + C_SACT_F;
    float* sOut = smemC + C_SOUT_F;
    int*   sQ   = (int*)(smemC + C_SQ_F);

    const int tid = threadIdx.x;
    const int bs  = blockIdx.x * BB;

    const float4* Wh4 = (const float4*)W_i2h;   // [256 rows][96 f4]; h-part at +32

    const int col   = tid & 255;
    const int khalf = (tid >> 8) & 1;           // valid for tid < 512

    // ---- one-time fills ---------------------------------------------------
    u64 wlo[8], whi[8];
    if (tid < 512) {
        const int k4base = khalf * 32;
        // register W: k4 local 0..7
        #pragma unroll
        for (int k4 = 0; k4 < 8; ++k4) {
            float4 v = Wh4[(size_t)col * 96 + 32 + k4base + k4];
            wlo[k4] = pack2(v.x, v.y);
            whi[k4] = pack2(v.z, v.w);
        }
        // smem W: k4 local 8..31 -> slot col*WPAD2 + khalf*24 + (k4-8)
        #pragma unroll 6
        for (int k4 = 8; k4 < 32; ++k4) {
            float4 v = Wh4[(size_t)col * 96 + 32 + k4base + k4];
            ulonglong2 p;
            p.x = pack2(v.x, v.y);
            p.y = pack2(v.z, v.w);
            sW2[(size_t)col * WPAD2 + khalf * 24 + (k4 - 8)] = p;
        }
        if (khalf == 0) {
            #pragma unroll
            for (int r = 0; r < BB; ++r)
                sH[r * 256 + col] = hidden[(size_t)(bs + r) * 256 + col];
            #pragma unroll
            for (int i = col; i < 4 * 256; i += 256)
                sWo[(i >> 8) * 260 + (i & 255)] = W_i2o[(i >> 8) * 384 + 128 + (i & 255)];
            #pragma unroll
            for (int i = col; i < 4 * 256; i += 256) sAct[i] = actions[i];
        }
    }
    __syncthreads();

    const ulonglong2* sWp = sW2 + (size_t)col * WPAD2 + khalf * 24 - 8;
    const float* hB = sH + khalf * 128;   // this half's K window base

    // X_proj prefetch (khalf1 threads own it; added into partial sums)
    float xp[8];
    if (tid < 512 && khalf == 1) {
        #pragma unroll
        for (int r = 0; r < 8; ++r)
            xp[r] = g_xproj[((size_t)0 * B_TOT + bs + r) * 256 + col];
    }
    float oxCur = 0.f;
    const int lane = tid - 512;                 // logits warp lane
    if (tid >= 512) oxCur = g_outx[((size_t)0 * B_TOT + bs) * 4 + lane];

    for (int t = 0; t < T_STEPS; ++t) {
        const int tn = (t + 1 < T_STEPS) ? (t + 1) : t;

        if (tid < 512) {
            u64 aL[8], aH[8];
            #pragma unroll
            for (int r = 0; r < 8; ++r) { aL[r] = 0ull; aH[r] = 0ull; }

            // ---- K part 1: register W (k4 local 0..7) ----
            #pragma unroll
            for (int k4 = 0; k4 < 8; ++k4) {
                #pragma unroll
                for (int r = 0; r < 8; ++r) {
                    ulonglong2 c = *(const ulonglong2*)(hB + r * 256 + k4 * 4);
                    ffma2(aL[r], wlo[k4], c.x);
                    ffma2(aH[r], whi[k4], c.y);
                }
            }
            // ---- K part 2: smem W (k4 local 8..31) ----
            #pragma unroll 4
            for (int k4 = 8; k4 < 32; ++k4) {
                ulonglong2 w = sWp[k4];
                #pragma unroll
                for (int r = 0; r < 8; ++r) {
                    ulonglong2 c = *(const ulonglong2*)(hB + r * 256 + k4 * 4);
                    ffma2(aL[r], w.x, c.x);
                    ffma2(aH[r], w.y, c.y);
                }
            }

            if (khalf == 1) {
                // partial (incl. X_proj which carries b_i2h) -> smem
                #pragma unroll
                for (int r = 0; r < 8; ++r)
                    sRed[r * 256 + col] = hsum2(aL[r]) + hsum2(aH[r]) + xp[r];
                // prefetch next step's X_proj
                #pragma unroll
                for (int r = 0; r < 8; ++r)
                    xp[r] = g_xproj[((size_t)tn * B_TOT + bs + r) * 256 + col];

                __syncthreads();   // B: partials + sQ ready

            } else {
                __syncthreads();   // B

                // ---- reduce + tanh + gate + commit ----
                #pragma unroll
                for (int r = 0; r < 8; ++r) {
                    float z = hsum2(aL[r]) + hsum2(aH[r]) + sRed[r * 256 + col];
                    float h = tanhf(z);
                    if (t == 0)
                        out[HS0_OFF + (size_t)(bs + r) * 256 + col] = h;
                    sH[r * 256 + col] = h * (1.0f + sAct[sQ[r] * 256 + col]);
                }
            }
        } else if (lane < 32) {
            // ---- logits warp: 4-way split accumulator ----
            const int r = lane >> 2, o = lane & 3;
            const float4* hp = (const float4*)(sH + r * 256);
            const float4* wp = (const float4*)(sWo + o * 260);
            float p0 = oxCur, p1 = 0.f, p2 = 0.f, p3 = 0.f;
            #pragma unroll 4
            for (int k4 = 0; k4 < 64; k4 += 4) {
                float4 h0 = hp[k4],     w0 = wp[k4];
                float4 h1 = hp[k4 + 1], w1 = wp[k4 + 1];
                float4 h2 = hp[k4 + 2], w2 = wp[k4 + 2];
                float4 h3 = hp[k4 + 3], w3 = wp[k4 + 3];
                p0 += h0.x * w0.x + h0.y * w0.y + h0.z * w0.z + h0.w * w0.w;
                p1 += h1.x * w1.x + h1.y * w1.y + h1.z * w1.z + h1.w * w1.w;
                p2 += h2.x * w2.x + h2.y * w2.y + h2.z * w2.z + h2.w * w2.w;
                p3 += h3.x * w3.x + h3.y * w3.y + h3.z * w3.z + h3.w * w3.w;
            }
            float acc = (p0 + p1) + (p2 + p3);
            sOut[lane] = acc;
            __syncwarp();
            if (o == 0) {
                float best = sOut[r * 4]; int q = 0;
                #pragma unroll
                for (int oo = 1; oo < 4; ++oo) {
                    float v = sOut[r * 4 + oo];
                    if (v > best) { best = v; q = oo; }
                }
                sQ[r] = q;
            }
            out[((size_t)t * B_TOT + bs) * 4 + lane] = acc;
            oxCur = g_outx[((size_t)tn * B_TOT + bs) * 4 + lane];

            __syncthreads();   // B
        } else {
            __syncthreads();   // B
        }

        __syncthreads();       // C: new h visible to everyone
    }
}

// ===========================================================================
extern "C" void kernel_launch(void* const* d_in, const int* in_sizes, int n_in,
                              void* d_out, int out_size)
{
    const float* inp     = (const float*)d_in[0];
    const float* hidden  = (const float*)d_in[1];
    const float* W_i2h   = (const float*)d_in[2];
    const float* b_i2h   = (const float*)d_in[3];
    const float* W_i2o   = (const float*)d_in[4];
    const float* b_i2o   = (const float*)d_in[5];
    const float* actions = (const float*)d_in[6];
    float* out = (float*)d_out;

    cudaFuncSetAttribute(xproj_kernel,
                         cudaFuncAttributeMaxDynamicSharedMemorySize, A_SMEM_BYTES);
    cudaFuncSetAttribute(rnn_seq_kernel,
                         cudaFuncAttributeMaxDynamicSharedMemorySize, C_SMEM_BYTES);

    xproj_kernel<<<(T_STEPS * B_TOT) / 128, 512, A_SMEM_BYTES>>>(inp, W_i2h, b_i2h);
    outx_kernel<<<(T_STEPS * B_TOT) / 256, 256>>>(inp, W_i2o, b_i2o);
    rnn_seq_kernel<<<NBLK_C, NTHR_C, C_SMEM_BYTES>>>(hidden, W_i2h, W_i2o,
                                                     actions, out);
}